// round 1
// baseline (speedup 1.0000x reference)
#include <cuda_runtime.h>
#include <math.h>

// Problem constants
#define BB   64
#define HH   28
#define WW   28
#define CC   384
#define TT   784      // HH*WW
#define HK   13       // (28-3)/2+1
#define TK   169      // 13*13
#define NHEAD 6
#define DD   64
#define EPSV 1e-3f

// Scratch (device globals; no runtime allocation allowed)
__device__ float g_qc[(size_t)BB*TT*CC];
__device__ float g_kc[(size_t)BB*TK*CC];
__device__ float g_vc[(size_t)BB*TK*CC];
__device__ float g_Q [(size_t)BB*TT*CC];
__device__ float g_K [(size_t)BB*TK*CC];
__device__ float g_V [(size_t)BB*TK*CC];
__device__ float g_O [(size_t)BB*TT*CC];

// ---------------------------------------------------------------------------
// Depthwise 3x3 conv (stride 1, SAME) + BN, for the q path.
// grid = BB*TT blocks, block = CC threads (one channel per thread, coalesced).
// ---------------------------------------------------------------------------
__global__ void dwbn_q_kernel(const float* __restrict__ x,
                              const float* __restrict__ w,
                              const float* __restrict__ gamma,
                              const float* __restrict__ beta,
                              const float* __restrict__ mean,
                              const float* __restrict__ var,
                              float* __restrict__ out)
{
    int c  = threadIdx.x;
    int sp = blockIdx.x;             // b*TT + t
    int b  = sp / TT;
    int t  = sp - b * TT;
    int y  = t / WW;
    int xw = t - y * WW;

    float acc = 0.f;
#pragma unroll
    for (int dy = 0; dy < 3; ++dy) {
        int yy = y + dy - 1;
        if (yy < 0 || yy >= HH) continue;
#pragma unroll
        for (int dx = 0; dx < 3; ++dx) {
            int xx = xw + dx - 1;
            if (xx < 0 || xx >= WW) continue;
            acc += x[((size_t)b*TT + yy*WW + xx)*CC + c] * w[(dy*3+dx)*CC + c];
        }
    }
    float sc = gamma[c] * rsqrtf(var[c] + EPSV);
    out[(size_t)sp*CC + c] = sc * (acc - mean[c]) + beta[c];
}

// ---------------------------------------------------------------------------
// Depthwise 3x3 conv (stride 2, VALID) + BN, fused for k and v (x read once).
// grid = BB*TK blocks, block = CC threads.
// ---------------------------------------------------------------------------
__global__ void dwbn_kv_kernel(const float* __restrict__ x,
                               const float* __restrict__ wk,
                               const float* __restrict__ kg,
                               const float* __restrict__ kb,
                               const float* __restrict__ km,
                               const float* __restrict__ kvv,
                               const float* __restrict__ wv,
                               const float* __restrict__ vg,
                               const float* __restrict__ vb,
                               const float* __restrict__ vm,
                               const float* __restrict__ vvv,
                               float* __restrict__ outk,
                               float* __restrict__ outv)
{
    int c  = threadIdx.x;
    int sp = blockIdx.x;             // b*TK + t
    int b  = sp / TK;
    int t  = sp - b * TK;
    int y  = t / HK;
    int xw = t - y * HK;

    float ak = 0.f, av = 0.f;
#pragma unroll
    for (int dy = 0; dy < 3; ++dy) {
#pragma unroll
        for (int dx = 0; dx < 3; ++dx) {
            float xv = x[((size_t)b*TT + (2*y+dy)*WW + (2*xw+dx))*CC + c];
            ak += xv * wk[(dy*3+dx)*CC + c];
            av += xv * wv[(dy*3+dx)*CC + c];
        }
    }
    float sck = kg[c] * rsqrtf(kvv[c] + EPSV);
    float scv = vg[c] * rsqrtf(vvv[c] + EPSV);
    outk[(size_t)sp*CC + c] = sck * (ak - km[c]) + kb[c];
    outv[(size_t)sp*CC + c] = scv * (av - vm[c]) + vb[c];
}

// ---------------------------------------------------------------------------
// C[M,384] = A[M,384] @ B[384,384] (+ optional bias).  M divisible by 64.
// 64x64 tile, BK=16, 256 threads, 4x4 per-thread microtile.
// ---------------------------------------------------------------------------
__global__ __launch_bounds__(256)
void gemm_nn(const float* __restrict__ A, const float* __restrict__ Bm,
             const float* __restrict__ bias, float* __restrict__ Cm)
{
    __shared__ float As[16][64];   // As[k][m]
    __shared__ float Bs[16][64];   // Bs[k][n]

    int tid = threadIdx.x;
    int br  = blockIdx.x * 64;
    int bc  = blockIdx.y * 64;
    int ty  = tid >> 4;            // 0..15 -> 4 rows each
    int tx  = tid & 15;            // 0..15 -> 4 cols each

    int a_row = tid >> 2;          // 0..63
    int a_k4  = (tid & 3) * 4;     // 0,4,8,12
    int b_kr  = tid >> 4;          // 0..15
    int b_n4  = (tid & 15) * 4;

    float acc[4][4] = {};

    for (int k0 = 0; k0 < CC; k0 += 16) {
        float4 avv = *(const float4*)&A [((size_t)(br + a_row))*CC + k0 + a_k4];
        float4 bvv = *(const float4*)&Bm[((size_t)(k0 + b_kr))*CC + bc + b_n4];
        As[a_k4+0][a_row] = avv.x;
        As[a_k4+1][a_row] = avv.y;
        As[a_k4+2][a_row] = avv.z;
        As[a_k4+3][a_row] = avv.w;
        *(float4*)&Bs[b_kr][b_n4] = bvv;
        __syncthreads();
#pragma unroll
        for (int k = 0; k < 16; ++k) {
            float4 aq = *(const float4*)&As[k][ty*4];
            float4 bq = *(const float4*)&Bs[k][tx*4];
            float a4[4] = {aq.x, aq.y, aq.z, aq.w};
            float b4[4] = {bq.x, bq.y, bq.z, bq.w};
#pragma unroll
            for (int i = 0; i < 4; ++i)
#pragma unroll
                for (int j = 0; j < 4; ++j)
                    acc[i][j] += a4[i] * b4[j];
        }
        __syncthreads();
    }

#pragma unroll
    for (int i = 0; i < 4; ++i) {
        size_t rowoff = ((size_t)(br + ty*4 + i))*CC + bc + tx*4;
#pragma unroll
        for (int j = 0; j < 4; ++j) {
            float v = acc[i][j];
            if (bias) v += bias[bc + tx*4 + j];
            Cm[rowoff + j] = v;
        }
    }
}

// ---------------------------------------------------------------------------
// Fused attention for one (b, head): S = Q K^T * scale, softmax, O = P V.
// Block handles 64 query rows; full K,V (169x64) resident in smem.
// grid = (13, BB*NHEAD), 256 threads, ~148.5 KB dynamic smem.
// ---------------------------------------------------------------------------
#define JP   176    // padded key count
#define SSTR 177    // S row stride (pad to break bank conflicts)
#define QSTR 65     // Q row stride

__global__ __launch_bounds__(256)
void attn_kernel(const float* __restrict__ Q, const float* __restrict__ K,
                 const float* __restrict__ V, float* __restrict__ O)
{
    extern __shared__ float sm[];
    float* Qs  = sm;                    // 64*65
    float* Kst = Qs  + 64*QSTR;         // [d][j]  64*176
    float* Vs  = Kst + 64*JP;           // [j][d]  176*64
    float* S   = Vs  + JP*64;           // 64*177

    int tid  = threadIdx.x;
    int bh   = blockIdx.y;
    int b    = bh / NHEAD;
    int h    = bh - b * NHEAD;
    int row0 = blockIdx.x * 64;
    const float scale = rsqrtf((float)CC);

    // Load Q tile (zero-pad out-of-range rows)
    for (int idx = tid; idx < 64*64; idx += 256) {
        int r = idx >> 6, d = idx & 63;
        int gr = row0 + r;
        Qs[r*QSTR + d] = (gr < TT) ? Q[((size_t)b*TT + gr)*CC + h*DD + d] : 0.f;
    }
    // Load K (transposed) and V; zero-pad j >= TK
    for (int idx = tid; idx < JP*64; idx += 256) {
        int j = idx >> 6, d = idx & 63;
        float kvv = 0.f, vvv = 0.f;
        if (j < TK) {
            kvv = K[((size_t)b*TK + j)*CC + h*DD + d];
            vvv = V[((size_t)b*TK + j)*CC + h*DD + d];
        }
        Kst[d*JP + j] = kvv;
        Vs [j*64 + d] = vvv;
    }
    __syncthreads();

    // S[64][176] = Qs[64][64] @ Kst  (each thread: 4 rows x 11 cols)
    {
        int ty = tid >> 4, tx = tid & 15;
        int r0 = ty * 4, j0 = tx * 11;
        float acc[4][11] = {};
        for (int k = 0; k < 64; ++k) {
            float a0 = Qs[(r0+0)*QSTR + k];
            float a1 = Qs[(r0+1)*QSTR + k];
            float a2 = Qs[(r0+2)*QSTR + k];
            float a3 = Qs[(r0+3)*QSTR + k];
#pragma unroll
            for (int j = 0; j < 11; ++j) {
                float bv = Kst[k*JP + j0 + j];
                acc[0][j] += a0 * bv;
                acc[1][j] += a1 * bv;
                acc[2][j] += a2 * bv;
                acc[3][j] += a3 * bv;
            }
        }
#pragma unroll
        for (int i = 0; i < 4; ++i)
#pragma unroll
            for (int j = 0; j < 11; ++j) {
                int jj = j0 + j;
                S[(r0+i)*SSTR + jj] = (jj < TK) ? acc[i][j] * scale : -1e30f;
            }
    }
    __syncthreads();

    // Row-wise softmax (8 warps x 8 rows)
    {
        int warp = tid >> 5, lane = tid & 31;
        for (int r = warp; r < 64; r += 8) {
            float m = -1e30f;
            for (int j = lane; j < JP; j += 32) m = fmaxf(m, S[r*SSTR + j]);
#pragma unroll
            for (int o = 16; o; o >>= 1) m = fmaxf(m, __shfl_xor_sync(~0u, m, o));
            float s = 0.f;
            for (int j = lane; j < JP; j += 32) {
                float e = __expf(S[r*SSTR + j] - m);
                S[r*SSTR + j] = e;
                s += e;
            }
#pragma unroll
            for (int o = 16; o; o >>= 1) s += __shfl_xor_sync(~0u, s, o);
            float inv = 1.f / s;
            for (int j = lane; j < JP; j += 32) S[r*SSTR + j] *= inv;
        }
    }
    __syncthreads();

    // O[64][64] = P[64][176] @ Vs[176][64]  (4x4 per thread)
    {
        int ty = tid >> 4, tx = tid & 15;
        int r0 = ty * 4, c0 = tx * 4;
        float acc[4][4] = {};
        for (int k = 0; k < JP; ++k) {
            float4 bq = *(const float4*)&Vs[k*64 + c0];
            float b4[4] = {bq.x, bq.y, bq.z, bq.w};
#pragma unroll
            for (int i = 0; i < 4; ++i) {
                float a = S[(r0+i)*SSTR + k];
#pragma unroll
                for (int j = 0; j < 4; ++j) acc[i][j] += a * b4[j];
            }
        }
#pragma unroll
        for (int i = 0; i < 4; ++i) {
            int gr = row0 + r0 + i;
            if (gr < TT) {
                size_t off = ((size_t)b*TT + gr)*CC + h*DD + c0;
#pragma unroll
                for (int j = 0; j < 4; ++j) O[off + j] = acc[i][j];
            }
        }
    }
}

static const int ATTN_SMEM = (64*QSTR + 64*JP + JP*64 + 64*SSTR) * (int)sizeof(float); // 152064

extern "C" void kernel_launch(void* const* d_in, const int* in_sizes, int n_in,
                              void* d_out, int out_size)
{
    (void)in_sizes; (void)n_in; (void)out_size;
    const float* x   = (const float*)d_in[0];
    const float* wq  = (const float*)d_in[1];
    const float* qg  = (const float*)d_in[2];
    const float* qb  = (const float*)d_in[3];
    const float* qm  = (const float*)d_in[4];
    const float* qv  = (const float*)d_in[5];
    const float* wk  = (const float*)d_in[6];
    const float* kg  = (const float*)d_in[7];
    const float* kb  = (const float*)d_in[8];
    const float* km  = (const float*)d_in[9];
    const float* kv_ = (const float*)d_in[10];
    const float* wv  = (const float*)d_in[11];
    const float* vg  = (const float*)d_in[12];
    const float* vb  = (const float*)d_in[13];
    const float* vm  = (const float*)d_in[14];
    const float* vv_ = (const float*)d_in[15];
    const float* Wq  = (const float*)d_in[16];
    const float* Wk  = (const float*)d_in[17];
    const float* Wv  = (const float*)d_in[18];
    const float* Wo  = (const float*)d_in[19];
    const float* bo  = (const float*)d_in[20];
    float* out = (float*)d_out;

    float *qc, *kc, *vc, *Qp, *Kp, *Vp, *Op;
    cudaGetSymbolAddress((void**)&qc, g_qc);
    cudaGetSymbolAddress((void**)&kc, g_kc);
    cudaGetSymbolAddress((void**)&vc, g_vc);
    cudaGetSymbolAddress((void**)&Qp, g_Q);
    cudaGetSymbolAddress((void**)&Kp, g_K);
    cudaGetSymbolAddress((void**)&Vp, g_V);
    cudaGetSymbolAddress((void**)&Op, g_O);

    // 1. conv projections
    dwbn_q_kernel <<<BB*TT, CC>>>(x, wq, qg, qb, qm, qv, qc);
    dwbn_kv_kernel<<<BB*TK, CC>>>(x, wk, kg, kb, km, kv_, wv, vg, vb, vm, vv_, kc, vc);

    // 2. dense projections
    dim3 gq(BB*TT/64, CC/64);   // 784 x 6
    dim3 gk(BB*TK/64, CC/64);   // 169 x 6
    gemm_nn<<<gq, 256>>>(qc, Wq, nullptr, Qp);
    gemm_nn<<<gk, 256>>>(kc, Wk, nullptr, Kp);
    gemm_nn<<<gk, 256>>>(vc, Wv, nullptr, Vp);

    // 3. attention
    cudaFuncSetAttribute(attn_kernel, cudaFuncAttributeMaxDynamicSharedMemorySize, ATTN_SMEM);
    dim3 ga((TT + 63)/64, BB*NHEAD);  // 13 x 384
    attn_kernel<<<ga, 256, ATTN_SMEM>>>(Qp, Kp, Vp, Op);

    // 4. output projection (+bias)
    gemm_nn<<<gq, 256>>>(Op, Wo, bo, out);
}

// round 2
// speedup vs baseline: 1.8831x; 1.8831x over previous
#include <cuda_runtime.h>
#include <math.h>
#include <stdint.h>

// Problem constants
#define BB   64
#define HH   28
#define WW   28
#define CC   384
#define TT   784      // HH*WW
#define HK   13       // (28-3)/2+1
#define TK   169      // 13*13
#define NHEAD 6
#define DD   64
#define EPSV 1e-3f

// Scratch (device globals; no runtime allocation allowed)
__device__ float g_qc[(size_t)BB*TT*CC];
__device__ float g_kc[(size_t)BB*TK*CC];
__device__ float g_vc[(size_t)BB*TK*CC];
__device__ float g_Q [(size_t)BB*TT*CC];
__device__ float g_K [(size_t)BB*TK*CC];
__device__ float g_V [(size_t)BB*TK*CC];
__device__ float g_O [(size_t)BB*TT*CC];

// ---------------------------------------------------------------------------
// TF32 helpers
// ---------------------------------------------------------------------------
__device__ __forceinline__ uint32_t f2tf(float x) {
    uint32_t r;
    asm("cvt.rna.tf32.f32 %0, %1;" : "=r"(r) : "f"(x));
    return r;
}

// D += A(16x8) * B(8x8), tf32 inputs, fp32 accumulate
__device__ __forceinline__ void mma8(float* c, const uint32_t* a, const uint32_t* b) {
    asm volatile(
        "mma.sync.aligned.m16n8k8.row.col.f32.tf32.tf32.f32 "
        "{%0,%1,%2,%3}, {%4,%5,%6,%7}, {%8,%9}, {%0,%1,%2,%3};"
        : "+f"(c[0]), "+f"(c[1]), "+f"(c[2]), "+f"(c[3])
        : "r"(a[0]), "r"(a[1]), "r"(a[2]), "r"(a[3]), "r"(b[0]), "r"(b[1]));
}

// ---------------------------------------------------------------------------
// Depthwise 3x3 conv (stride 1, SAME) + BN, q path.
// ---------------------------------------------------------------------------
__global__ void dwbn_q_kernel(const float* __restrict__ x,
                              const float* __restrict__ w,
                              const float* __restrict__ gamma,
                              const float* __restrict__ beta,
                              const float* __restrict__ mean,
                              const float* __restrict__ var,
                              float* __restrict__ out)
{
    int c  = threadIdx.x;
    int sp = blockIdx.x;
    int b  = sp / TT;
    int t  = sp - b * TT;
    int y  = t / WW;
    int xw = t - y * WW;

    float acc = 0.f;
#pragma unroll
    for (int dy = 0; dy < 3; ++dy) {
        int yy = y + dy - 1;
        if (yy < 0 || yy >= HH) continue;
#pragma unroll
        for (int dx = 0; dx < 3; ++dx) {
            int xx = xw + dx - 1;
            if (xx < 0 || xx >= WW) continue;
            acc += x[((size_t)b*TT + yy*WW + xx)*CC + c] * w[(dy*3+dx)*CC + c];
        }
    }
    float sc = gamma[c] * rsqrtf(var[c] + EPSV);
    out[(size_t)sp*CC + c] = sc * (acc - mean[c]) + beta[c];
}

// ---------------------------------------------------------------------------
// Depthwise 3x3 conv (stride 2, VALID) + BN, fused for k and v.
// ---------------------------------------------------------------------------
__global__ void dwbn_kv_kernel(const float* __restrict__ x,
                               const float* __restrict__ wk,
                               const float* __restrict__ kg,
                               const float* __restrict__ kb,
                               const float* __restrict__ km,
                               const float* __restrict__ kvv,
                               const float* __restrict__ wv,
                               const float* __restrict__ vg,
                               const float* __restrict__ vb,
                               const float* __restrict__ vm,
                               const float* __restrict__ vvv,
                               float* __restrict__ outk,
                               float* __restrict__ outv)
{
    int c  = threadIdx.x;
    int sp = blockIdx.x;
    int b  = sp / TK;
    int t  = sp - b * TK;
    int y  = t / HK;
    int xw = t - y * HK;

    float ak = 0.f, av = 0.f;
#pragma unroll
    for (int dy = 0; dy < 3; ++dy) {
#pragma unroll
        for (int dx = 0; dx < 3; ++dx) {
            float xv = x[((size_t)b*TT + (2*y+dy)*WW + (2*xw+dx))*CC + c];
            ak += xv * wk[(dy*3+dx)*CC + c];
            av += xv * wv[(dy*3+dx)*CC + c];
        }
    }
    float sck = kg[c] * rsqrtf(kvv[c] + EPSV);
    float scv = vg[c] * rsqrtf(vvv[c] + EPSV);
    outk[(size_t)sp*CC + c] = sck * (ak - km[c]) + kb[c];
    outv[(size_t)sp*CC + c] = scv * (av - vm[c]) + vb[c];
}

// ---------------------------------------------------------------------------
// TF32 tensor-core GEMM: C[M,384] = A[M,384] @ B[384,384] (+bias).
// Block tile 128x64, BK=32, 128 threads (4 warps), warp tile 32x64.
// smem strides chosen for conflict-free mma fragment loads:
//   ASTR=36 (=4 mod 32: bank=4m+k bijective), BSTR=72 (=8 mod 32: 8k+n bijective)
// ---------------------------------------------------------------------------
#define GBM 128
#define GBN 64
#define GBK 32
#define ASTR 36
#define BSTR 72

__global__ __launch_bounds__(128)
void gemm_tf32(const float* __restrict__ A, const float* __restrict__ Bm,
               const float* __restrict__ bias, float* __restrict__ Cm, int M)
{
    __shared__ uint32_t As[GBM*ASTR];
    __shared__ uint32_t Bs[GBK*BSTR];

    int tid  = threadIdx.x;
    int warp = tid >> 5;
    int lane = tid & 31;
    int g    = lane >> 2;     // group id 0..7
    int tg   = lane & 3;      // thread-in-group 0..3
    int bm   = blockIdx.x * GBM;
    int bn   = blockIdx.y * GBN;
    int wm   = warp * 32;

    float acc[2][8][4];
#pragma unroll
    for (int a = 0; a < 2; ++a)
#pragma unroll
        for (int b = 0; b < 8; ++b)
#pragma unroll
            for (int c = 0; c < 4; ++c) acc[a][b][c] = 0.f;

    for (int k0 = 0; k0 < CC; k0 += GBK) {
        // Stage A tile (convert to tf32 at store)
#pragma unroll
        for (int i = 0; i < 8; ++i) {
            int idx = i*128 + tid;
            int r = idx >> 3, c = (idx & 7) << 2;
            int gr = bm + r;
            float4 v = make_float4(0.f,0.f,0.f,0.f);
            if (gr < M) v = *(const float4*)&A[(size_t)gr*CC + k0 + c];
            As[r*ASTR + c + 0] = f2tf(v.x);
            As[r*ASTR + c + 1] = f2tf(v.y);
            As[r*ASTR + c + 2] = f2tf(v.z);
            As[r*ASTR + c + 3] = f2tf(v.w);
        }
        // Stage B tile
#pragma unroll
        for (int i = 0; i < 4; ++i) {
            int idx = i*128 + tid;
            int r = idx >> 4, c = (idx & 15) << 2;
            float4 v = *(const float4*)&Bm[(size_t)(k0 + r)*CC + bn + c];
            Bs[r*BSTR + c + 0] = f2tf(v.x);
            Bs[r*BSTR + c + 1] = f2tf(v.y);
            Bs[r*BSTR + c + 2] = f2tf(v.z);
            Bs[r*BSTR + c + 3] = f2tf(v.w);
        }
        __syncthreads();

#pragma unroll
        for (int kk = 0; kk < GBK; kk += 8) {
            uint32_t af[2][4];
#pragma unroll
            for (int mi = 0; mi < 2; ++mi) {
                int rb = wm + mi*16;
                af[mi][0] = As[(rb + g    )*ASTR + kk + tg    ];
                af[mi][1] = As[(rb + g + 8)*ASTR + kk + tg    ];
                af[mi][2] = As[(rb + g    )*ASTR + kk + tg + 4];
                af[mi][3] = As[(rb + g + 8)*ASTR + kk + tg + 4];
            }
#pragma unroll
            for (int ni = 0; ni < 8; ++ni) {
                uint32_t bf[2];
                bf[0] = Bs[(kk + tg    )*BSTR + ni*8 + g];
                bf[1] = Bs[(kk + tg + 4)*BSTR + ni*8 + g];
                mma8(acc[0][ni], af[0], bf);
                mma8(acc[1][ni], af[1], bf);
            }
        }
        __syncthreads();
    }

    // Epilogue
#pragma unroll
    for (int mi = 0; mi < 2; ++mi) {
#pragma unroll
        for (int i = 0; i < 2; ++i) {
            int gr = bm + wm + mi*16 + g + i*8;
            if (gr >= M) continue;
#pragma unroll
            for (int ni = 0; ni < 8; ++ni) {
                int col = bn + ni*8 + tg*2;
                float2 v;
                v.x = acc[mi][ni][i*2 + 0];
                v.y = acc[mi][ni][i*2 + 1];
                if (bias) { v.x += bias[col]; v.y += bias[col+1]; }
                *(float2*)&Cm[(size_t)gr*CC + col] = v;
            }
        }
    }
}

// ---------------------------------------------------------------------------
// Fused attention with TF32 mma: S = Q K^T * scale, softmax, O = P V.
// Block: 64 query rows, full K/V (169 keys) in smem. 256 threads = 8 warps,
// split 4 (m-bands of 16 rows) x 2 (n-halves).
// smem strides (conflict-free frag access):
//   QSTR2=68 (=4 mod 32), KSTR=184 (=24 mod 32: 24k+j bijective for k<4,j<8),
//   VSTR=72 (=8 mod 32), PSTR=196 (=4 mod 32).
// ---------------------------------------------------------------------------
#define JP    176
#define QSTR2 68
#define KSTR  184
#define VSTR  72
#define PSTR  196

__global__ __launch_bounds__(256)
void attn_tf32(const float* __restrict__ Q, const float* __restrict__ K,
               const float* __restrict__ V, float* __restrict__ O)
{
    extern __shared__ uint32_t sm[];
    uint32_t* Qs = sm;                       // 64*68
    uint32_t* Ks = Qs + 64*QSTR2;            // [d][j] 64*184
    uint32_t* Vs = Ks + 64*KSTR;             // [j][d] 176*72
    float*    Sm = (float*)(Vs + JP*VSTR);   // 64*196

    int tid  = threadIdx.x;
    int warp = tid >> 5;
    int lane = tid & 31;
    int g    = lane >> 2;
    int tg   = lane & 3;
    int bh   = blockIdx.y;
    int b    = bh / NHEAD;
    int h    = bh - b * NHEAD;
    int row0 = blockIdx.x * 64;
    int wm   = (warp & 3) * 16;   // m band
    int whalf= warp >> 2;         // n half
    const float scale = rsqrtf((float)CC);

    // Load Q tile (64x64) -> tf32
    for (int idx = tid; idx < 64*16; idx += 256) {
        int r = idx >> 4, d = (idx & 15) << 2;
        int gr = row0 + r;
        float4 v = make_float4(0.f,0.f,0.f,0.f);
        if (gr < TT) v = *(const float4*)&Q[((size_t)b*TT + gr)*CC + h*DD + d];
        Qs[r*QSTR2 + d + 0] = f2tf(v.x);
        Qs[r*QSTR2 + d + 1] = f2tf(v.y);
        Qs[r*QSTR2 + d + 2] = f2tf(v.z);
        Qs[r*QSTR2 + d + 3] = f2tf(v.w);
    }
    // Load K (transposed to [d][j]) and V ([j][d]); zero-pad j >= TK
    for (int idx = tid; idx < JP*16; idx += 256) {
        int j = idx >> 4, d = (idx & 15) << 2;
        float4 kv = make_float4(0.f,0.f,0.f,0.f);
        float4 vv = make_float4(0.f,0.f,0.f,0.f);
        if (j < TK) {
            kv = *(const float4*)&K[((size_t)b*TK + j)*CC + h*DD + d];
            vv = *(const float4*)&V[((size_t)b*TK + j)*CC + h*DD + d];
        }
        Ks[(d+0)*KSTR + j] = f2tf(kv.x);
        Ks[(d+1)*KSTR + j] = f2tf(kv.y);
        Ks[(d+2)*KSTR + j] = f2tf(kv.z);
        Ks[(d+3)*KSTR + j] = f2tf(kv.w);
        Vs[j*VSTR + d + 0] = f2tf(vv.x);
        Vs[j*VSTR + d + 1] = f2tf(vv.y);
        Vs[j*VSTR + d + 2] = f2tf(vv.z);
        Vs[j*VSTR + d + 3] = f2tf(vv.w);
    }
    __syncthreads();

    // ---- Matmul 1: S[64][176] = Q @ K^T  (each warp: 16 rows x 88 cols) ----
    {
        int jbase = whalf * 88;
        float sacc[11][4];
#pragma unroll
        for (int i = 0; i < 11; ++i)
#pragma unroll
            for (int c = 0; c < 4; ++c) sacc[i][c] = 0.f;

#pragma unroll
        for (int kk = 0; kk < 64; kk += 8) {
            uint32_t af[4];
            af[0] = Qs[(wm + g    )*QSTR2 + kk + tg    ];
            af[1] = Qs[(wm + g + 8)*QSTR2 + kk + tg    ];
            af[2] = Qs[(wm + g    )*QSTR2 + kk + tg + 4];
            af[3] = Qs[(wm + g + 8)*QSTR2 + kk + tg + 4];
#pragma unroll
            for (int ni = 0; ni < 11; ++ni) {
                uint32_t bf[2];
                bf[0] = Ks[(kk + tg    )*KSTR + jbase + ni*8 + g];
                bf[1] = Ks[(kk + tg + 4)*KSTR + jbase + ni*8 + g];
                mma8(sacc[ni], af, bf);
            }
        }
        // write scores (scaled), mask padded key columns
#pragma unroll
        for (int ni = 0; ni < 11; ++ni) {
#pragma unroll
            for (int i = 0; i < 2; ++i) {
                int r   = wm + g + i*8;
                int col = jbase + ni*8 + tg*2;
                Sm[r*PSTR + col    ] = (col     < TK) ? sacc[ni][i*2+0]*scale : -1e30f;
                Sm[r*PSTR + col + 1] = (col + 1 < TK) ? sacc[ni][i*2+1]*scale : -1e30f;
            }
        }
    }
    __syncthreads();

    // ---- Softmax (8 warps x 8 rows); final P stored as tf32 bits ----
    {
        uint32_t* Sp = (uint32_t*)Sm;
        for (int r = warp; r < 64; r += 8) {
            float m = -1e30f;
            for (int j = lane; j < JP; j += 32) m = fmaxf(m, Sm[r*PSTR + j]);
#pragma unroll
            for (int o = 16; o; o >>= 1) m = fmaxf(m, __shfl_xor_sync(~0u, m, o));
            float s = 0.f;
            for (int j = lane; j < JP; j += 32) {
                float e = __expf(Sm[r*PSTR + j] - m);
                Sm[r*PSTR + j] = e;
                s += e;
            }
#pragma unroll
            for (int o = 16; o; o >>= 1) s += __shfl_xor_sync(~0u, s, o);
            float inv = 1.f / s;
            for (int j = lane; j < JP; j += 32)
                Sp[r*PSTR + j] = f2tf(Sm[r*PSTR + j] * inv);
        }
    }
    __syncthreads();

    // ---- Matmul 2: O[64][64] = P[64][176] @ V[176][64] ----
    {
        const uint32_t* Sp = (const uint32_t*)Sm;
        int nbase = whalf * 32;
        float oacc[4][4];
#pragma unroll
        for (int i = 0; i < 4; ++i)
#pragma unroll
            for (int c = 0; c < 4; ++c) oacc[i][c] = 0.f;

#pragma unroll
        for (int kk = 0; kk < JP; kk += 8) {
            uint32_t af[4];
            af[0] = Sp[(wm + g    )*PSTR + kk + tg    ];
            af[1] = Sp[(wm + g + 8)*PSTR + kk + tg    ];
            af[2] = Sp[(wm + g    )*PSTR + kk + tg + 4];
            af[3] = Sp[(wm + g + 8)*PSTR + kk + tg + 4];
#pragma unroll
            for (int ni = 0; ni < 4; ++ni) {
                uint32_t bf[2];
                bf[0] = Vs[(kk + tg    )*VSTR + nbase + ni*8 + g];
                bf[1] = Vs[(kk + tg + 4)*VSTR + nbase + ni*8 + g];
                mma8(oacc[ni], af, bf);
            }
        }
#pragma unroll
        for (int ni = 0; ni < 4; ++ni) {
#pragma unroll
            for (int i = 0; i < 2; ++i) {
                int gr = row0 + wm + g + i*8;
                if (gr >= TT) continue;
                int col = nbase + ni*8 + tg*2;
                float2 v;
                v.x = oacc[ni][i*2+0];
                v.y = oacc[ni][i*2+1];
                *(float2*)&O[((size_t)b*TT + gr)*CC + h*DD + col] = v;
            }
        }
    }
}

static const int ATTN_SMEM = (64*QSTR2 + 64*KSTR + JP*VSTR + 64*PSTR) * (int)sizeof(uint32_t);

extern "C" void kernel_launch(void* const* d_in, const int* in_sizes, int n_in,
                              void* d_out, int out_size)
{
    (void)in_sizes; (void)n_in; (void)out_size;
    const float* x   = (const float*)d_in[0];
    const float* wq  = (const float*)d_in[1];
    const float* qg  = (const float*)d_in[2];
    const float* qb  = (const float*)d_in[3];
    const float* qm  = (const float*)d_in[4];
    const float* qv  = (const float*)d_in[5];
    const float* wk  = (const float*)d_in[6];
    const float* kg  = (const float*)d_in[7];
    const float* kb  = (const float*)d_in[8];
    const float* km  = (const float*)d_in[9];
    const float* kv_ = (const float*)d_in[10];
    const float* wv  = (const float*)d_in[11];
    const float* vg  = (const float*)d_in[12];
    const float* vb  = (const float*)d_in[13];
    const float* vm  = (const float*)d_in[14];
    const float* vv_ = (const float*)d_in[15];
    const float* Wq  = (const float*)d_in[16];
    const float* Wk  = (const float*)d_in[17];
    const float* Wv  = (const float*)d_in[18];
    const float* Wo  = (const float*)d_in[19];
    const float* bo  = (const float*)d_in[20];
    float* out = (float*)d_out;

    float *qc, *kc, *vc, *Qp, *Kp, *Vp, *Op;
    cudaGetSymbolAddress((void**)&qc, g_qc);
    cudaGetSymbolAddress((void**)&kc, g_kc);
    cudaGetSymbolAddress((void**)&vc, g_vc);
    cudaGetSymbolAddress((void**)&Qp, g_Q);
    cudaGetSymbolAddress((void**)&Kp, g_K);
    cudaGetSymbolAddress((void**)&Vp, g_V);
    cudaGetSymbolAddress((void**)&Op, g_O);

    // 1. conv projections
    dwbn_q_kernel <<<BB*TT, CC>>>(x, wq, qg, qb, qm, qv, qc);
    dwbn_kv_kernel<<<BB*TK, CC>>>(x, wk, kg, kb, km, kv_, wv, vg, vb, vm, vv_, kc, vc);

    // 2. dense projections (tf32 tensor cores)
    const int MQ = BB*TT;   // 50176
    const int MK = BB*TK;   // 10816
    dim3 gq((MQ + GBM - 1)/GBM, CC/GBN);   // 392 x 6
    dim3 gk((MK + GBM - 1)/GBM, CC/GBN);   // 85 x 6
    gemm_tf32<<<gq, 128>>>(qc, Wq, nullptr, Qp, MQ);
    gemm_tf32<<<gk, 128>>>(kc, Wk, nullptr, Kp, MK);
    gemm_tf32<<<gk, 128>>>(vc, Wv, nullptr, Vp, MK);

    // 3. attention (tf32 tensor cores)
    cudaFuncSetAttribute(attn_tf32, cudaFuncAttributeMaxDynamicSharedMemorySize, ATTN_SMEM);
    dim3 ga((TT + 63)/64, BB*NHEAD);   // 13 x 384
    attn_tf32<<<ga, 256, ATTN_SMEM>>>(Qp, Kp, Vp, Op);

    // 4. output projection (+bias, tf32 tensor cores)
    gemm_tf32<<<gq, 128>>>(Op, Wo, bo, out, MQ);
}

// round 4
// speedup vs baseline: 3.3342x; 1.7706x over previous
#include <cuda_runtime.h>
#include <math.h>
#include <stdint.h>

// Problem constants
#define BB   64
#define HH   28
#define WW   28
#define CC   384
#define TT   784      // HH*WW
#define HK   13       // (28-3)/2+1
#define TK   169      // 13*13
#define NHEAD 6
#define DD   64
#define EPSV 1e-3f

// Scratch (device globals; no runtime allocation allowed)
__device__ float g_qc[(size_t)BB*TT*CC];
__device__ float g_kc[(size_t)BB*TK*CC];
__device__ float g_vc[(size_t)BB*TK*CC];
__device__ float g_Q [(size_t)BB*TT*CC];
__device__ float g_K [(size_t)BB*TK*CC];
__device__ float g_V [(size_t)BB*TK*CC];
__device__ float g_O [(size_t)BB*TT*CC];

// ---------------------------------------------------------------------------
// TF32 / async helpers
// ---------------------------------------------------------------------------
__device__ __forceinline__ uint32_t f2tf(float x) {
    uint32_t r;
    asm("cvt.rna.tf32.f32 %0, %1;" : "=r"(r) : "f"(x));
    return r;
}

__device__ __forceinline__ void mma8(float* c, const uint32_t* a, const uint32_t* b) {
    asm volatile(
        "mma.sync.aligned.m16n8k8.row.col.f32.tf32.tf32.f32 "
        "{%0,%1,%2,%3}, {%4,%5,%6,%7}, {%8,%9}, {%0,%1,%2,%3};"
        : "+f"(c[0]), "+f"(c[1]), "+f"(c[2]), "+f"(c[3])
        : "r"(a[0]), "r"(a[1]), "r"(a[2]), "r"(a[3]), "r"(b[0]), "r"(b[1]));
}

__device__ __forceinline__ void cp16(uint32_t dst_smem, const void* src, bool pred) {
    int sz = pred ? 16 : 0;
    asm volatile("cp.async.ca.shared.global [%0], [%1], 16, %2;"
                 :: "r"(dst_smem), "l"(src), "r"(sz));
}
__device__ __forceinline__ void cp_commit() { asm volatile("cp.async.commit_group;"); }

// ---------------------------------------------------------------------------
// Depthwise 3x3 conv (stride 1, SAME) + BN, q path.
// ---------------------------------------------------------------------------
__global__ void dwbn_q_kernel(const float* __restrict__ x,
                              const float* __restrict__ w,
                              const float* __restrict__ gamma,
                              const float* __restrict__ beta,
                              const float* __restrict__ mean,
                              const float* __restrict__ var,
                              float* __restrict__ out)
{
    int c  = threadIdx.x;
    int sp = blockIdx.x;
    int b  = sp / TT;
    int t  = sp - b * TT;
    int y  = t / WW;
    int xw = t - y * WW;

    float acc = 0.f;
#pragma unroll
    for (int dy = 0; dy < 3; ++dy) {
        int yy = y + dy - 1;
        if (yy < 0 || yy >= HH) continue;
#pragma unroll
        for (int dx = 0; dx < 3; ++dx) {
            int xx = xw + dx - 1;
            if (xx < 0 || xx >= WW) continue;
            acc += x[((size_t)b*TT + yy*WW + xx)*CC + c] * w[(dy*3+dx)*CC + c];
        }
    }
    float sc = gamma[c] * rsqrtf(var[c] + EPSV);
    out[(size_t)sp*CC + c] = sc * (acc - mean[c]) + beta[c];
}

// ---------------------------------------------------------------------------
// Depthwise 3x3 conv (stride 2, VALID) + BN, fused for k and v.
// ---------------------------------------------------------------------------
__global__ void dwbn_kv_kernel(const float* __restrict__ x,
                               const float* __restrict__ wk,
                               const float* __restrict__ kg,
                               const float* __restrict__ kb,
                               const float* __restrict__ km,
                               const float* __restrict__ kvv,
                               const float* __restrict__ wv,
                               const float* __restrict__ vg,
                               const float* __restrict__ vb,
                               const float* __restrict__ vm,
                               const float* __restrict__ vvv,
                               float* __restrict__ outk,
                               float* __restrict__ outv)
{
    int c  = threadIdx.x;
    int sp = blockIdx.x;
    int b  = sp / TK;
    int t  = sp - b * TK;
    int y  = t / HK;
    int xw = t - y * HK;

    float ak = 0.f, av = 0.f;
#pragma unroll
    for (int dy = 0; dy < 3; ++dy) {
#pragma unroll
        for (int dx = 0; dx < 3; ++dx) {
            float xv = x[((size_t)b*TT + (2*y+dy)*WW + (2*xw+dx))*CC + c];
            ak += xv * wk[(dy*3+dx)*CC + c];
            av += xv * wv[(dy*3+dx)*CC + c];
        }
    }
    float sck = kg[c] * rsqrtf(kvv[c] + EPSV);
    float scv = vg[c] * rsqrtf(vvv[c] + EPSV);
    outk[(size_t)sp*CC + c] = sck * (ak - km[c]) + kb[c];
    outv[(size_t)sp*CC + c] = scv * (av - vm[c]) + vb[c];
}

// ---------------------------------------------------------------------------
// TF32 GEMM v2 (fixed B-loader): C[M,384] = A[M,384] @ B[384,384] (+bias).
// 256 threads (8 warps, 2m x 4n), block tile 128x128, warp tile 64x32,
// BK=16, cp.async double-buffered. fp32 staged in smem; cvt->tf32 at frag load.
// ---------------------------------------------------------------------------
#define GBM 128
#define GBN 128
#define GBK 16
#define ASTR 20
#define BSTR 136
#define NT   (CC/GBK)   // 24

__global__ __launch_bounds__(256, 2)
void gemm_tf32(const float* __restrict__ A, const float* __restrict__ Bm,
               const float* __restrict__ bias, float* __restrict__ Cm, int M)
{
    __shared__ float As[2][GBM*ASTR];
    __shared__ float Bs[2][GBK*BSTR];

    int tid  = threadIdx.x;
    int warp = tid >> 5;
    int lane = tid & 31;
    int g    = lane >> 2;
    int tg   = lane & 3;
    int bm   = blockIdx.x * GBM;
    int bn   = blockIdx.y * GBN;
    int wm   = (warp >> 2) * 64;
    int wn   = (warp & 3) * 32;

    // load indices
    int a_r = tid >> 2;           // 0..63 (two iters -> 128 rows)
    int a_q = (tid & 3) * 4;      // k offset
    int b_r = tid >> 4;           // 0..15
    int b_q = (tid & 15) * 4;     // n offset (two iters -> 128 cols)

    uint32_t sA[2], sB[2];
    sA[0] = (uint32_t)__cvta_generic_to_shared(&As[0][0]);
    sA[1] = (uint32_t)__cvta_generic_to_shared(&As[1][0]);
    sB[0] = (uint32_t)__cvta_generic_to_shared(&Bs[0][0]);
    sB[1] = (uint32_t)__cvta_generic_to_shared(&Bs[1][0]);

    float acc[4][4][4];
#pragma unroll
    for (int mf = 0; mf < 4; ++mf)
#pragma unroll
        for (int nf = 0; nf < 4; ++nf)
#pragma unroll
            for (int c = 0; c < 4; ++c) acc[mf][nf][c] = 0.f;

    auto load_stage = [&](int t, int buf) {
#pragma unroll
        for (int i = 0; i < 2; ++i) {
            int r  = i*64 + a_r;
            int gr = bm + r;
            bool p = (gr < M);
            const float* src = &A[(size_t)(p ? gr : 0)*CC + t*GBK + a_q];
            cp16(sA[buf] + (uint32_t)(r*ASTR + a_q)*4u, src, p);
        }
#pragma unroll
        for (int i = 0; i < 2; ++i) {
            int col = i*64 + b_q;                               // FIX: full 128 cols
            const float* src = &Bm[(size_t)(t*GBK + b_r)*CC + bn + col];
            cp16(sB[buf] + (uint32_t)(b_r*BSTR + col)*4u, src, true);
        }
        cp_commit();
    };

    load_stage(0, 0);

    for (int t = 0; t < NT; ++t) {
        int buf = t & 1;
        if (t + 1 < NT) {
            load_stage(t + 1, buf ^ 1);
            asm volatile("cp.async.wait_group 1;");
        } else {
            asm volatile("cp.async.wait_group 0;");
        }
        __syncthreads();

        const float* Ab = As[buf];
        const float* Bb = Bs[buf];
#pragma unroll
        for (int kk = 0; kk < GBK; kk += 8) {
            uint32_t af[4][4];
#pragma unroll
            for (int mf = 0; mf < 4; ++mf) {
                int rb = wm + mf*16;
                af[mf][0] = f2tf(Ab[(rb + g    )*ASTR + kk + tg    ]);
                af[mf][1] = f2tf(Ab[(rb + g + 8)*ASTR + kk + tg    ]);
                af[mf][2] = f2tf(Ab[(rb + g    )*ASTR + kk + tg + 4]);
                af[mf][3] = f2tf(Ab[(rb + g + 8)*ASTR + kk + tg + 4]);
            }
#pragma unroll
            for (int nf = 0; nf < 4; ++nf) {
                uint32_t bf[2];
                bf[0] = f2tf(Bb[(kk + tg    )*BSTR + wn + nf*8 + g]);
                bf[1] = f2tf(Bb[(kk + tg + 4)*BSTR + wn + nf*8 + g]);
#pragma unroll
                for (int mf = 0; mf < 4; ++mf)
                    mma8(acc[mf][nf], af[mf], bf);
            }
        }
        __syncthreads();
    }

    // Epilogue
#pragma unroll
    for (int mf = 0; mf < 4; ++mf) {
#pragma unroll
        for (int i = 0; i < 2; ++i) {
            int gr = bm + wm + mf*16 + g + i*8;
            if (gr >= M) continue;
#pragma unroll
            for (int nf = 0; nf < 4; ++nf) {
                int col = bn + wn + nf*8 + tg*2;
                float2 v;
                v.x = acc[mf][nf][i*2 + 0];
                v.y = acc[mf][nf][i*2 + 1];
                if (bias) { v.x += bias[col]; v.y += bias[col+1]; }
                *(float2*)&Cm[(size_t)gr*CC + col] = v;
            }
        }
    }
}

// ---------------------------------------------------------------------------
// Attention v3: register-resident S/P. 8 warps x 16 q-rows = 128 rows/block.
// smem: K^T (64x176, stride 184) + V (176x64, stride 72) = 97.8KB -> 2 blk/SM.
// ---------------------------------------------------------------------------
#define JP    176
#define NKC   22     // JP/8
#define KSTR  184
#define VSTR  72

__global__ __launch_bounds__(256, 2)
void attn_tf32(const float* __restrict__ Q, const float* __restrict__ K,
               const float* __restrict__ V, float* __restrict__ O)
{
    extern __shared__ uint32_t sm[];
    uint32_t* Ks = sm;               // [d][j] 64*184
    uint32_t* Vs = sm + 64*KSTR;     // [j][d] 176*72

    int tid  = threadIdx.x;
    int warp = tid >> 5;
    int lane = tid & 31;
    int g    = lane >> 2;
    int tg   = lane & 3;
    int bh   = blockIdx.y;
    int b    = bh / NHEAD;
    int h    = bh - b * NHEAD;
    int row0 = blockIdx.x * 128;
    const float scale = rsqrtf((float)CC);

    // Cooperative K^T / V load (tf32), zero-pad j >= TK
    for (int idx = tid; idx < JP*16; idx += 256) {
        int j = idx >> 4, d = (idx & 15) << 2;
        float4 kv = make_float4(0.f,0.f,0.f,0.f);
        float4 vv = make_float4(0.f,0.f,0.f,0.f);
        if (j < TK) {
            kv = *(const float4*)&K[((size_t)b*TK + j)*CC + h*DD + d];
            vv = *(const float4*)&V[((size_t)b*TK + j)*CC + h*DD + d];
        }
        Ks[(d+0)*KSTR + j] = f2tf(kv.x);
        Ks[(d+1)*KSTR + j] = f2tf(kv.y);
        Ks[(d+2)*KSTR + j] = f2tf(kv.z);
        Ks[(d+3)*KSTR + j] = f2tf(kv.w);
        Vs[j*VSTR + d + 0] = f2tf(vv.x);
        Vs[j*VSTR + d + 1] = f2tf(vv.y);
        Vs[j*VSTR + d + 2] = f2tf(vv.z);
        Vs[j*VSTR + d + 3] = f2tf(vv.w);
    }
    __syncthreads();

    // ---- S = Q K^T : each warp 16 rows x 176 cols, acc in registers ----
    int r0 = row0 + warp * 16;
    const float* Qb = Q + (size_t)b*TT*CC + (size_t)h*DD;

    float p[NKC][4];
#pragma unroll
    for (int ni = 0; ni < NKC; ++ni)
#pragma unroll
        for (int c = 0; c < 4; ++c) p[ni][c] = 0.f;

#pragma unroll
    for (int kc = 0; kc < 8; ++kc) {
        int kk = kc * 8;
        int ra = r0 + g, rb = r0 + g + 8;
        uint32_t af[4];
        af[0] = f2tf((ra < TT) ? Qb[(size_t)ra*CC + kk + tg    ] : 0.f);
        af[1] = f2tf((rb < TT) ? Qb[(size_t)rb*CC + kk + tg    ] : 0.f);
        af[2] = f2tf((ra < TT) ? Qb[(size_t)ra*CC + kk + tg + 4] : 0.f);
        af[3] = f2tf((rb < TT) ? Qb[(size_t)rb*CC + kk + tg + 4] : 0.f);
#pragma unroll
        for (int ni = 0; ni < NKC; ++ni) {
            uint32_t bf[2];
            bf[0] = Ks[(kk + tg    )*KSTR + ni*8 + g];
            bf[1] = Ks[(kk + tg + 4)*KSTR + ni*8 + g];
            mma8(p[ni], af, bf);
        }
    }

    // ---- scale + mask + softmax in registers ----
    float m0 = -1e30f, m1 = -1e30f;
#pragma unroll
    for (int ni = 0; ni < NKC; ++ni) {
        int c0 = ni*8 + 2*tg, c1 = c0 + 1;
        p[ni][0] = (c0 < TK) ? p[ni][0]*scale : -1e30f;
        p[ni][1] = (c1 < TK) ? p[ni][1]*scale : -1e30f;
        p[ni][2] = (c0 < TK) ? p[ni][2]*scale : -1e30f;
        p[ni][3] = (c1 < TK) ? p[ni][3]*scale : -1e30f;
        m0 = fmaxf(m0, fmaxf(p[ni][0], p[ni][1]));
        m1 = fmaxf(m1, fmaxf(p[ni][2], p[ni][3]));
    }
    m0 = fmaxf(m0, __shfl_xor_sync(~0u, m0, 1));
    m0 = fmaxf(m0, __shfl_xor_sync(~0u, m0, 2));
    m1 = fmaxf(m1, __shfl_xor_sync(~0u, m1, 1));
    m1 = fmaxf(m1, __shfl_xor_sync(~0u, m1, 2));

    float s0 = 0.f, s1 = 0.f;
#pragma unroll
    for (int ni = 0; ni < NKC; ++ni) {
        p[ni][0] = __expf(p[ni][0] - m0);
        p[ni][1] = __expf(p[ni][1] - m0);
        p[ni][2] = __expf(p[ni][2] - m1);
        p[ni][3] = __expf(p[ni][3] - m1);
        s0 += p[ni][0] + p[ni][1];
        s1 += p[ni][2] + p[ni][3];
    }
    s0 += __shfl_xor_sync(~0u, s0, 1);
    s0 += __shfl_xor_sync(~0u, s0, 2);
    s1 += __shfl_xor_sync(~0u, s1, 1);
    s1 += __shfl_xor_sync(~0u, s1, 2);
    float i0 = 1.f / s0, i1 = 1.f / s1;

#pragma unroll
    for (int ni = 0; ni < NKC; ++ni) {
        p[ni][0] = __uint_as_float(f2tf(p[ni][0] * i0));
        p[ni][1] = __uint_as_float(f2tf(p[ni][1] * i0));
        p[ni][2] = __uint_as_float(f2tf(p[ni][2] * i1));
        p[ni][3] = __uint_as_float(f2tf(p[ni][3] * i1));
    }

    // ---- O = P V : two 32-col halves ----
    int srcA = (lane & ~3) | (tg >> 1);
    int srcB = srcA + 2;
    int odd  = tg & 1;

#pragma unroll
    for (int half = 0; half < 2; ++half) {
        float oacc[4][4];
#pragma unroll
        for (int nf = 0; nf < 4; ++nf)
#pragma unroll
            for (int c = 0; c < 4; ++c) oacc[nf][c] = 0.f;

#pragma unroll
        for (int kc = 0; kc < NKC; ++kc) {
            float x0 = __shfl_sync(~0u, p[kc][0], srcA);
            float x1 = __shfl_sync(~0u, p[kc][1], srcA);
            float y0 = __shfl_sync(~0u, p[kc][0], srcB);
            float y1 = __shfl_sync(~0u, p[kc][1], srcB);
            float z0 = __shfl_sync(~0u, p[kc][2], srcA);
            float z1 = __shfl_sync(~0u, p[kc][3], srcA);
            float w0 = __shfl_sync(~0u, p[kc][2], srcB);
            float w1 = __shfl_sync(~0u, p[kc][3], srcB);
            uint32_t af[4];
            af[0] = __float_as_uint(odd ? x1 : x0);
            af[1] = __float_as_uint(odd ? z1 : z0);
            af[2] = __float_as_uint(odd ? y1 : y0);
            af[3] = __float_as_uint(odd ? w1 : w0);

            int kk = kc * 8;
#pragma unroll
            for (int nf = 0; nf < 4; ++nf) {
                uint32_t bf[2];
                bf[0] = Vs[(kk + tg    )*VSTR + half*32 + nf*8 + g];
                bf[1] = Vs[(kk + tg + 4)*VSTR + half*32 + nf*8 + g];
                mma8(oacc[nf], af, bf);
            }
        }

#pragma unroll
        for (int nf = 0; nf < 4; ++nf) {
#pragma unroll
            for (int i = 0; i < 2; ++i) {
                int gr = r0 + g + i*8;
                if (gr >= TT) continue;
                int col = h*DD + half*32 + nf*8 + tg*2;
                float2 v;
                v.x = oacc[nf][i*2 + 0];
                v.y = oacc[nf][i*2 + 1];
                *(float2*)&O[((size_t)b*TT + gr)*CC + col] = v;
            }
        }
    }
}

static const int ATTN_SMEM = (64*KSTR + JP*VSTR) * (int)sizeof(uint32_t);  // 97792

extern "C" void kernel_launch(void* const* d_in, const int* in_sizes, int n_in,
                              void* d_out, int out_size)
{
    (void)in_sizes; (void)n_in; (void)out_size;
    const float* x   = (const float*)d_in[0];
    const float* wq  = (const float*)d_in[1];
    const float* qg  = (const float*)d_in[2];
    const float* qb  = (const float*)d_in[3];
    const float* qm  = (const float*)d_in[4];
    const float* qv  = (const float*)d_in[5];
    const float* wk  = (const float*)d_in[6];
    const float* kg  = (const float*)d_in[7];
    const float* kb  = (const float*)d_in[8];
    const float* km  = (const float*)d_in[9];
    const float* kv_ = (const float*)d_in[10];
    const float* wv  = (const float*)d_in[11];
    const float* vg  = (const float*)d_in[12];
    const float* vb  = (const float*)d_in[13];
    const float* vm  = (const float*)d_in[14];
    const float* vv_ = (const float*)d_in[15];
    const float* Wq  = (const float*)d_in[16];
    const float* Wk  = (const float*)d_in[17];
    const float* Wv  = (const float*)d_in[18];
    const float* Wo  = (const float*)d_in[19];
    const float* bo  = (const float*)d_in[20];
    float* out = (float*)d_out;

    float *qc, *kc, *vc, *Qp, *Kp, *Vp, *Op;
    cudaGetSymbolAddress((void**)&qc, g_qc);
    cudaGetSymbolAddress((void**)&kc, g_kc);
    cudaGetSymbolAddress((void**)&vc, g_vc);
    cudaGetSymbolAddress((void**)&Qp, g_Q);
    cudaGetSymbolAddress((void**)&Kp, g_K);
    cudaGetSymbolAddress((void**)&Vp, g_V);
    cudaGetSymbolAddress((void**)&Op, g_O);

    // 1. conv projections
    dwbn_q_kernel <<<BB*TT, CC>>>(x, wq, qg, qb, qm, qv, qc);
    dwbn_kv_kernel<<<BB*TK, CC>>>(x, wk, kg, kb, km, kv_, wv, vg, vb, vm, vv_, kc, vc);

    // 2. dense projections
    const int MQ = BB*TT;   // 50176
    const int MK = BB*TK;   // 10816
    dim3 gq((MQ + GBM - 1)/GBM, CC/GBN);   // 392 x 3
    dim3 gk((MK + GBM - 1)/GBM, CC/GBN);   // 85 x 3
    gemm_tf32<<<gq, 256>>>(qc, Wq, nullptr, Qp, MQ);
    gemm_tf32<<<gk, 256>>>(kc, Wk, nullptr, Kp, MK);
    gemm_tf32<<<gk, 256>>>(vc, Wv, nullptr, Vp, MK);

    // 3. attention (register-resident S/P)
    cudaFuncSetAttribute(attn_tf32, cudaFuncAttributeMaxDynamicSharedMemorySize, ATTN_SMEM);
    dim3 ga((TT + 127)/128, BB*NHEAD);   // 7 x 384
    attn_tf32<<<ga, 256, ATTN_SMEM>>>(Qp, Kp, Vp, Op);

    // 4. output projection (+bias)
    gemm_tf32<<<gq, 256>>>(Op, Wo, bo, out, MQ);
}